// round 13
// baseline (speedup 1.0000x reference)
#include <cuda_runtime.h>
#include <cuda_fp16.h>
#include <cstdint>

// ---------------------------------------------------------------------------
// a [B=16, C=64, H=256, W=256] fp32
//   q,k,v = 1x1 conv;  per (b,c): S=QK^T/16, P=softmax(S), O=PV
//   out = a + W_adapt * O
// Round 13: R12 + unrolled attention mma loops (S ks-loop unroll 4, PV
// ks-loop full) to give ptxas a software-pipelining window over the
// ldsm->mma dependency chains. qkv unchanged (clean A/B on attn).
// ---------------------------------------------------------------------------

#define N_ELEM (16 * 64 * 256 * 256)

__device__ __half g_q[N_ELEM];   // [b*64+o][h*256+w]
__device__ __half g_k[N_ELEM];
__device__ __half g_v[N_ELEM];

// ============================ helpers ======================================

__device__ __forceinline__ uint32_t su32(const void* p) {
    return (uint32_t)__cvta_generic_to_shared(p);
}
__device__ __forceinline__ void ldsm4(uint32_t* r, uint32_t addr) {
    asm volatile("ldmatrix.sync.aligned.m8n8.x4.shared.b16 {%0,%1,%2,%3}, [%4];"
        : "=r"(r[0]), "=r"(r[1]), "=r"(r[2]), "=r"(r[3]) : "r"(addr));
}
__device__ __forceinline__ void ldsm4t(uint32_t* r, uint32_t addr) {
    asm volatile("ldmatrix.sync.aligned.m8n8.x4.trans.shared.b16 {%0,%1,%2,%3}, [%4];"
        : "=r"(r[0]), "=r"(r[1]), "=r"(r[2]), "=r"(r[3]) : "r"(addr));
}
__device__ __forceinline__ void mma16816(float* d, const uint32_t* a, const uint32_t* b) {
    asm volatile("mma.sync.aligned.m16n8k16.row.col.f32.f16.f16.f32 "
        "{%0,%1,%2,%3}, {%4,%5,%6,%7}, {%8,%9}, {%0,%1,%2,%3};"
        : "+f"(d[0]), "+f"(d[1]), "+f"(d[2]), "+f"(d[3])
        : "r"(a[0]), "r"(a[1]), "r"(a[2]), "r"(a[3]), "r"(b[0]), "r"(b[1]));
}
__device__ __forceinline__ float ex2f(float x) {
    float y; asm("ex2.approx.f32 %0, %1;" : "=f"(y) : "f"(x)); return y;
}
__device__ __forceinline__ uint32_t packh2(float lo, float hi) {
    __half2 h = __floats2half2_rn(lo, hi);
    return *(uint32_t*)&h;
}
__device__ __forceinline__ void cp16(uint32_t dst, const void* src) {
    asm volatile("cp.async.cg.shared.global [%0], [%1], 16;"
        :: "r"(dst), "l"(src));
}
#define CP_COMMIT() asm volatile("cp.async.commit_group;" ::: "memory")
#define CP_WAIT0()  asm volatile("cp.async.wait_group 0;" ::: "memory")

// ======================= Kernel A: QKV (HMMA, C = W * a^T) =================
// (unchanged from R12)
#define QKV_STG_OFF 58112
#define QKV_SMEM_BYTES (58112 + 32768)

__global__ __launch_bounds__(256, 2) void qkv_kernel(
    const float* __restrict__ a,
    const float* __restrict__ Wq, const float* __restrict__ bq,
    const float* __restrict__ Wk, const float* __restrict__ bk,
    const float* __restrict__ Wv, const float* __restrict__ bv)
{
    extern __shared__ char sm[];
    char* sA = sm;
    char* sW = sm + 32768;
    float* sB = (float*)(sm + 57344);
    char* sStage = sm + QKV_STG_OFF;

    const int tid = threadIdx.x;
    const int b = blockIdx.x >> 8;
    const int P0 = (blockIdx.x & 255) << 8;

    for (int i = tid; i < 6144; i += 256) {
        const int m = i >> 11, j = i & 2047;
        const int o = j >> 5, c2 = j & 31;
        const float* W = (m == 0) ? Wq : ((m == 1) ? Wk : Wv);
        const float f0 = W[o * 64 + 2 * c2];
        const float f1 = W[o * 64 + 2 * c2 + 1];
        const int u = c2 >> 2;
        *(uint32_t*)(sW + m * 8192 + o * 128 + ((u ^ (o & 7)) << 4) + (c2 & 3) * 4)
            = packh2(f0, f1);
    }
    if (tid < 192) {
        const float* bb = (tid < 64) ? bq : ((tid < 128) ? bk : bv);
        sB[tid] = bb[tid & 63];
    }
    // a tile, channel-major [c][p]: 16 x (LDG.128 + STS.64) per thread
    {
        const float4* asrc = (const float4*)(a + (size_t)b * 64 * 65536 + P0);
        #pragma unroll
        for (int j = 0; j < 16; j++) {
            const int idx = j * 256 + tid;
            const int cch = idx >> 6;
            const int f4 = idx & 63;
            const float4 v = asrc[(size_t)cch * 16384 + f4];
            const int u = f4 >> 1;
            uint2 pk;
            pk.x = packh2(v.x, v.y);
            pk.y = packh2(v.z, v.w);
            *(uint2*)(sA + cch * 512 + ((u ^ (cch & 7)) << 4) + (f4 & 1) * 8) = pk;
        }
    }
    __syncthreads();

    const int wid = tid >> 5, lane = tid & 31;
    const int wp0 = wid * 32;
    const int sel = lane >> 3, wl = lane & 7;
    const int lr = lane >> 2, lc = lane & 3;
    const uint32_t sAb = su32(sA), sWb = su32(sW);

    for (int mat = 0; mat < 3; mat++) {
        float c[4][4][4];
        #pragma unroll
        for (int mt = 0; mt < 4; mt++)
            #pragma unroll
            for (int n = 0; n < 4; n++)
                #pragma unroll
                for (int q = 0; q < 4; q++) c[mt][n][q] = 0.f;

        #pragma unroll
        for (int np = 0; np < 2; np++) {
            uint32_t bfr[4][4];
            #pragma unroll
            for (int ks = 0; ks < 4; ks++) {
                const int rB = 16 * ks + wl + ((sel & 1) << 3);
                const int uB = wid * 4 + 2 * np + (sel >> 1);
                ldsm4t(bfr[ks], sAb + rB * 512 + ((uB ^ (rB & 7)) << 4));
            }
            #pragma unroll
            for (int mt = 0; mt < 4; mt++) {
                #pragma unroll
                for (int ks = 0; ks < 4; ks++) {
                    uint32_t afr[4];
                    const int rA = mt * 16 + wl + ((sel & 1) << 3);
                    const int uA = 2 * ks + (sel >> 1);
                    ldsm4(afr, sWb + mat * 8192 + rA * 128 + ((uA ^ (rA & 7)) << 4));
                    mma16816(c[mt][2 * np],     afr, bfr[ks]);
                    mma16816(c[mt][2 * np + 1], afr, bfr[ks] + 2);
                }
            }
        }

        if (mat > 0) __syncthreads();

        #pragma unroll
        for (int mt = 0; mt < 4; mt++) {
            const int o0 = mt * 16 + lr, o1 = o0 + 8;
            const float b0 = sB[mat * 64 + o0];
            const float b1 = sB[mat * 64 + o1];
            #pragma unroll
            for (int j = 0; j < 4; j++) {
                const int colp = wp0 + j * 8 + 2 * lc;
                const int pu = colp >> 3, pb = (colp & 7) * 2;
                *(uint32_t*)(sStage + o0 * 512 + ((pu ^ (o0 & 7)) << 4) + pb)
                    = packh2(c[mt][j][0] + b0, c[mt][j][1] + b0);
                *(uint32_t*)(sStage + o1 * 512 + ((pu ^ (o1 & 7)) << 4) + pb)
                    = packh2(c[mt][j][2] + b1, c[mt][j][3] + b1);
            }
        }
        __syncthreads();

        __half* g = (mat == 0) ? g_q : ((mat == 1) ? g_k : g_v);
        #pragma unroll
        for (int oo = 0; oo < 8; oo++) {
            const int o = wid * 8 + oo;
            const uint4 val = *(const uint4*)(sStage + o * 512 + ((lane ^ (o & 7)) << 4));
            *(uint4*)(g + (size_t)(b * 64 + o) * 65536 + P0 + lane * 8) = val;
        }
    }
}

// ======================= Kernel B: attention ===============================
// R10 structure; S ks-loop unroll 4 + PV ks-loop full unroll for pipelining.
#define AT_Q    0
#define AT_K    32768
#define AT_P0   98304
#define AT_SUM  114688
#define ATTN_SMEM_BYTES 115712

__global__ __launch_bounds__(256, 2) void attn_kernel(
    const float* __restrict__ a,
    const float* __restrict__ Wad,
    float* __restrict__ out)
{
    extern __shared__ char sm[];
    float* sSum = (float*)(sm + AT_SUM);

    const int tid = threadIdx.x, wid = tid >> 5, lane = tid & 31;
    const int rg = wid & 1, cg = wid >> 1;
    const int R0 = rg * 32;
    const int C0 = cg * 32;
    const int V0 = cg * 64;
    const int bc = blockIdx.x >> 2, qq = blockIdx.x & 3;
    const size_t base = (size_t)bc * 65536;

    const int sel = lane >> 3, wl = lane & 7;
    const int lr = lane >> 2, lc = lane & 3;
    const uint32_t sQb = su32(sm + AT_Q), sKb = su32(sm + AT_K), sP0b = su32(sm + AT_P0);

    // ---- async fills: Q (64 rows) + K half 0 (128 rows) ----
    {
        const __half* src = g_q + base + (size_t)qq * 16384;
        #pragma unroll
        for (int t = 0; t < 8; t++) {
            const int i = t * 256 + tid;
            const int r = i >> 5, u = i & 31;
            cp16(sQb + r * 512 + ((u ^ (r & 7)) << 4), src + i * 8);
        }
    }
    {
        const __half* src = g_k + base;
        #pragma unroll
        for (int t = 0; t < 16; t++) {
            const int i = t * 256 + tid;
            const int r = i >> 5, u = i & 31;
            cp16(sKb + r * 512 + ((u ^ (r & 7)) << 4), src + i * 8);
        }
    }
    CP_COMMIT();

    float sacc[2][2] = {{0.f, 0.f}, {0.f, 0.f}};
    const float KS = 1.4426950408889634f / 16.f;   // log2(e)/16

    CP_WAIT0();
    __syncthreads();

    // ================= S phases (both K halves), c regs only ===============
    for (int kh = 0; kh < 2; kh++) {
        float c[2][4][4];
        #pragma unroll
        for (int mi = 0; mi < 2; mi++)
            #pragma unroll
            for (int n = 0; n < 4; n++)
                #pragma unroll
                for (int q = 0; q < 4; q++) c[mi][n][q] = 0.f;

        #pragma unroll 4
        for (int ks = 0; ks < 16; ks++) {
            uint32_t a0[4], a1[4];
            {
                const int r = R0 + wl + ((sel & 1) << 3);
                const int u = 2 * ks + (sel >> 1);
                ldsm4(a0, sQb + r * 512 + ((u ^ (r & 7)) << 4));
                const int r2 = r + 16;
                ldsm4(a1, sQb + r2 * 512 + ((u ^ (r2 & 7)) << 4));
            }
            #pragma unroll
            for (int nb = 0; nb < 2; nb++) {
                uint32_t bb[4];
                const int rB = C0 + nb * 16 + wl + ((sel >> 1) << 3);
                const int uB = 2 * ks + (sel & 1);
                ldsm4(bb, sKb + rB * 512 + ((uB ^ (rB & 7)) << 4));
                mma16816(c[0][2 * nb],     a0, bb);
                mma16816(c[0][2 * nb + 1], a0, bb + 2);
                mma16816(c[1][2 * nb],     a1, bb);
                mma16816(c[1][2 * nb + 1], a1, bb + 2);
            }
        }
        __syncthreads();   // K half (and Q, when kh=1) reads done

        if (kh == 0) {
            const __half* src = g_k + base + 32768;   // K half 1
            #pragma unroll
            for (int t = 0; t < 16; t++) {
                const int i = t * 256 + tid;
                const int r = i >> 5, u = i & 31;
                cp16(sKb + r * 512 + ((u ^ (r & 7)) << 4), src + i * 8);
            }
        } else {
            const __half* src = g_v + base;           // V chunk 0 -> ring buf 0
            #pragma unroll
            for (int t = 0; t < 8; t++) {
                const int i = t * 256 + tid;
                const int r = i >> 5, u = i & 31;
                cp16(sKb + r * 512 + ((u ^ (r & 7)) << 4), src + i * 8);
            }
        }
        CP_COMMIT();

        const uint32_t pBase = (kh == 0) ? (uint32_t)AT_P0 : (uint32_t)AT_Q;
        #pragma unroll
        for (int mi = 0; mi < 2; mi++) {
            const int rb = R0 + 16 * mi + lr, rb8 = rb + 8;
            #pragma unroll
            for (int ni = 0; ni < 4; ni++) {
                const float e0 = ex2f(fmaf(c[mi][ni][0], KS, -8.f));
                const float e1 = ex2f(fmaf(c[mi][ni][1], KS, -8.f));
                const float e2 = ex2f(fmaf(c[mi][ni][2], KS, -8.f));
                const float e3 = ex2f(fmaf(c[mi][ni][3], KS, -8.f));
                sacc[mi][0] += e0 + e1;
                sacc[mi][1] += e2 + e3;
                const int u = (C0 >> 3) + ni;
                *(uint32_t*)(sm + pBase + rb * 256 + ((u ^ (rb & 7)) << 4) + 4 * lc)
                    = packh2(e0, e1);
                *(uint32_t*)(sm + pBase + rb8 * 256 + ((u ^ (rb8 & 7)) << 4) + 4 * lc)
                    = packh2(e2, e3);
            }
        }
        CP_WAIT0();
        __syncthreads();   // next tile ready; P visible
    }

    // ================= PV: 4 chunks of 64 V-rows, 2x32KB ring ==============
    float o[2][8][4];
    #pragma unroll
    for (int mi = 0; mi < 2; mi++)
        #pragma unroll
        for (int n = 0; n < 8; n++)
            #pragma unroll
            for (int q = 0; q < 4; q++) o[mi][n][q] = 0.f;

    for (int ch = 0; ch < 4; ch++) {
        if (ch < 3) {
            const __half* src = g_v + base + (size_t)(ch + 1) * 16384;
            const uint32_t dst = sKb + (uint32_t)(((ch + 1) & 1) * 32768);
            #pragma unroll
            for (int t = 0; t < 8; t++) {
                const int i = t * 256 + tid;
                const int r = i >> 5, u = i & 31;
                cp16(dst + r * 512 + ((u ^ (r & 7)) << 4), src + i * 8);
            }
            CP_COMMIT();
        }

        const uint32_t vbuf = sKb + (uint32_t)((ch & 1) * 32768);
        const uint32_t pb = (ch < 2) ? sP0b : sQb;
        const int ko = (ch & 1) * 4;

        #pragma unroll
        for (int ks = 0; ks < 4; ks++) {
            uint32_t p0[4], p1[4];
            {
                const int r = R0 + wl + ((sel & 1) << 3);
                const int u = 2 * (ko + ks) + (sel >> 1);
                ldsm4(p0, pb + r * 256 + ((u ^ (r & 7)) << 4));
                const int r2 = r + 16;
                ldsm4(p1, pb + r2 * 256 + ((u ^ (r2 & 7)) << 4));
            }
            #pragma unroll
            for (int nt = 0; nt < 4; nt++) {
                uint32_t bb[4];
                const int rV = 16 * ks + wl + ((sel & 1) << 3);
                const int uV = cg * 8 + 2 * nt + (sel >> 1);
                ldsm4t(bb, vbuf + rV * 512 + ((uV ^ (rV & 7)) << 4));
                mma16816(o[0][2 * nt],     p0, bb);
                mma16816(o[0][2 * nt + 1], p0, bb + 2);
                mma16816(o[1][2 * nt],     p1, bb);
                mma16816(o[1][2 * nt + 1], p1, bb + 2);
            }
        }

        if (ch < 3) {
            CP_WAIT0();
            __syncthreads();
        }
    }

    // ---- quad reduction: full row sums ----
    #pragma unroll
    for (int mi = 0; mi < 2; mi++) {
        #pragma unroll
        for (int hh = 0; hh < 2; hh++) {
            sacc[mi][hh] += __shfl_xor_sync(0xffffffffu, sacc[mi][hh], 1);
            sacc[mi][hh] += __shfl_xor_sync(0xffffffffu, sacc[mi][hh], 2);
        }
    }
    if (lc == 0) {
        #pragma unroll
        for (int mi = 0; mi < 2; mi++) {
            sSum[(R0 + 16 * mi + lr) * 4 + cg]     = sacc[mi][0];
            sSum[(R0 + 16 * mi + lr + 8) * 4 + cg] = sacc[mi][1];
        }
    }
    __syncthreads();

    // ---- epilogue: out = a + wad/rowsum * O ----
    const float wad = Wad[0];
    #pragma unroll
    for (int mi = 0; mi < 2; mi++) {
        const int rb = R0 + 16 * mi + lr;
        const float f0 = wad / (sSum[rb * 4] + sSum[rb * 4 + 1]
                              + sSum[rb * 4 + 2] + sSum[rb * 4 + 3]);
        const float f1 = wad / (sSum[(rb + 8) * 4] + sSum[(rb + 8) * 4 + 1]
                              + sSum[(rb + 8) * 4 + 2] + sSum[(rb + 8) * 4 + 3]);
        const int h0 = qq * 64 + rb;
        #pragma unroll
        for (int ni = 0; ni < 8; ni++) {
            const int col = V0 + ni * 8 + 2 * lc;
            const size_t i0 = base + (size_t)h0 * 256 + col;
            const float2 a0 = *(const float2*)(a + i0);
            float2 v0;
            v0.x = a0.x + f0 * o[mi][ni][0];
            v0.y = a0.y + f0 * o[mi][ni][1];
            *(float2*)(out + i0) = v0;
            const size_t i1 = i0 + 8 * 256;
            const float2 a1 = *(const float2*)(a + i1);
            float2 v1;
            v1.x = a1.x + f1 * o[mi][ni][2];
            v1.y = a1.y + f1 * o[mi][ni][3];
            *(float2*)(out + i1) = v1;
        }
    }
}

// ---------------------------------------------------------------------------
extern "C" void kernel_launch(void* const* d_in, const int* in_sizes, int n_in,
                              void* d_out, int out_size)
{
    const float* a   = (const float*)d_in[0];
    const float* Wq  = (const float*)d_in[1];
    const float* bq  = (const float*)d_in[2];
    const float* Wk  = (const float*)d_in[3];
    const float* bk  = (const float*)d_in[4];
    const float* Wv  = (const float*)d_in[5];
    const float* bv  = (const float*)d_in[6];
    const float* Wad = (const float*)d_in[7];
    float* out = (float*)d_out;

    cudaFuncSetAttribute(qkv_kernel,
                         cudaFuncAttributeMaxDynamicSharedMemorySize, QKV_SMEM_BYTES);
    cudaFuncSetAttribute(attn_kernel,
                         cudaFuncAttributeMaxDynamicSharedMemorySize, ATTN_SMEM_BYTES);
    cudaFuncSetAttribute(attn_kernel,
                         cudaFuncAttributePreferredSharedMemoryCarveout, 100);

    qkv_kernel<<<16 * 256, 256, QKV_SMEM_BYTES>>>(a, Wq, bq, Wk, bk, Wv, bv);
    attn_kernel<<<4096, 256, ATTN_SMEM_BYTES>>>(a, Wad, out);
}

// round 17
// speedup vs baseline: 1.5356x; 1.5356x over previous
#include <cuda_runtime.h>
#include <cuda_fp16.h>
#include <cstdint>

// ---------------------------------------------------------------------------
// a [B=16, C=64, H=256, W=256] fp32
//   q,k,v = 1x1 conv;  per (b,c): S=QK^T/16, P=softmax(S), O=PV
//   out = a + W_adapt * O
// Round 14: R12 structure (rolled loops — R13 unroll regressed hard) with the
// S-phase moved to fp8 (e4m3) Q/K via mma.m16n8k32: S mma + ldsm halved,
// Q/K bytes halved end-to-end. P and V stay fp16 (PV untouched).
// ---------------------------------------------------------------------------

#define N_ELEM (16 * 64 * 256 * 256)

__device__ unsigned char g_q[N_ELEM];  // e4m3 bits, [b*64+o][h*256+w]
__device__ unsigned char g_k[N_ELEM];  // e4m3 bits
__device__ __half        g_v[N_ELEM];  // fp16

// ============================ helpers ======================================

__device__ __forceinline__ uint32_t su32(const void* p) {
    return (uint32_t)__cvta_generic_to_shared(p);
}
__device__ __forceinline__ void ldsm4(uint32_t* r, uint32_t addr) {
    asm volatile("ldmatrix.sync.aligned.m8n8.x4.shared.b16 {%0,%1,%2,%3}, [%4];"
        : "=r"(r[0]), "=r"(r[1]), "=r"(r[2]), "=r"(r[3]) : "r"(addr));
}
__device__ __forceinline__ void ldsm4t(uint32_t* r, uint32_t addr) {
    asm volatile("ldmatrix.sync.aligned.m8n8.x4.trans.shared.b16 {%0,%1,%2,%3}, [%4];"
        : "=r"(r[0]), "=r"(r[1]), "=r"(r[2]), "=r"(r[3]) : "r"(addr));
}
__device__ __forceinline__ void mma16816(float* d, const uint32_t* a, const uint32_t* b) {
    asm volatile("mma.sync.aligned.m16n8k16.row.col.f32.f16.f16.f32 "
        "{%0,%1,%2,%3}, {%4,%5,%6,%7}, {%8,%9}, {%0,%1,%2,%3};"
        : "+f"(d[0]), "+f"(d[1]), "+f"(d[2]), "+f"(d[3])
        : "r"(a[0]), "r"(a[1]), "r"(a[2]), "r"(a[3]), "r"(b[0]), "r"(b[1]));
}
// fp8 e4m3 MMA: same operand register shapes as the fp16 k16 form.
__device__ __forceinline__ void mma16832(float* d, const uint32_t* a, const uint32_t* b) {
    asm volatile("mma.sync.aligned.m16n8k32.row.col.f32.e4m3.e4m3.f32 "
        "{%0,%1,%2,%3}, {%4,%5,%6,%7}, {%8,%9}, {%0,%1,%2,%3};"
        : "+f"(d[0]), "+f"(d[1]), "+f"(d[2]), "+f"(d[3])
        : "r"(a[0]), "r"(a[1]), "r"(a[2]), "r"(a[3]), "r"(b[0]), "r"(b[1]));
}
__device__ __forceinline__ float ex2f(float x) {
    float y; asm("ex2.approx.f32 %0, %1;" : "=f"(y) : "f"(x)); return y;
}
__device__ __forceinline__ uint32_t packh2(float lo, float hi) {
    __half2 h = __floats2half2_rn(lo, hi);
    return *(uint32_t*)&h;
}
__device__ __forceinline__ uint16_t pack8(float lo, float hi) {
    uint16_t v;
    asm("cvt.rn.satfinite.e4m3x2.f32 %0, %1, %2;" : "=h"(v) : "f"(hi), "f"(lo));
    return v;
}
__device__ __forceinline__ void cp16(uint32_t dst, const void* src) {
    asm volatile("cp.async.cg.shared.global [%0], [%1], 16;"
        :: "r"(dst), "l"(src));
}
#define CP_COMMIT() asm volatile("cp.async.commit_group;" ::: "memory")
#define CP_WAIT0()  asm volatile("cp.async.wait_group 0;" ::: "memory")

// ======================= Kernel A: QKV (HMMA, C = W * a^T) =================
// R12 structure; q,k staged/stored as e4m3 (256B/channel), v as fp16.
#define QKV_STG_OFF 58112
#define QKV_SMEM_BYTES (58112 + 32768)

__global__ __launch_bounds__(256, 2) void qkv_kernel(
    const float* __restrict__ a,
    const float* __restrict__ Wq, const float* __restrict__ bq,
    const float* __restrict__ Wk, const float* __restrict__ bk,
    const float* __restrict__ Wv, const float* __restrict__ bv)
{
    extern __shared__ char sm[];
    char* sA = sm;
    char* sW = sm + 32768;
    float* sB = (float*)(sm + 57344);
    char* sStage = sm + QKV_STG_OFF;

    const int tid = threadIdx.x;
    const int b = blockIdx.x >> 8;
    const int P0 = (blockIdx.x & 255) << 8;

    for (int i = tid; i < 6144; i += 256) {
        const int m = i >> 11, j = i & 2047;
        const int o = j >> 5, c2 = j & 31;
        const float* W = (m == 0) ? Wq : ((m == 1) ? Wk : Wv);
        const float f0 = W[o * 64 + 2 * c2];
        const float f1 = W[o * 64 + 2 * c2 + 1];
        const int u = c2 >> 2;
        *(uint32_t*)(sW + m * 8192 + o * 128 + ((u ^ (o & 7)) << 4) + (c2 & 3) * 4)
            = packh2(f0, f1);
    }
    if (tid < 192) {
        const float* bb = (tid < 64) ? bq : ((tid < 128) ? bk : bv);
        sB[tid] = bb[tid & 63];
    }
    // a tile, channel-major [c][p]: 16 x (LDG.128 + STS.64) per thread
    {
        const float4* asrc = (const float4*)(a + (size_t)b * 64 * 65536 + P0);
        #pragma unroll
        for (int j = 0; j < 16; j++) {
            const int idx = j * 256 + tid;
            const int cch = idx >> 6;
            const int f4 = idx & 63;
            const float4 v = asrc[(size_t)cch * 16384 + f4];
            const int u = f4 >> 1;
            uint2 pk;
            pk.x = packh2(v.x, v.y);
            pk.y = packh2(v.z, v.w);
            *(uint2*)(sA + cch * 512 + ((u ^ (cch & 7)) << 4) + (f4 & 1) * 8) = pk;
        }
    }
    __syncthreads();

    const int wid = tid >> 5, lane = tid & 31;
    const int wp0 = wid * 32;
    const int sel = lane >> 3, wl = lane & 7;
    const int lr = lane >> 2, lc = lane & 3;
    const uint32_t sAb = su32(sA), sWb = su32(sW);

    for (int mat = 0; mat < 3; mat++) {
        float c[4][4][4];
        #pragma unroll
        for (int mt = 0; mt < 4; mt++)
            #pragma unroll
            for (int n = 0; n < 4; n++)
                #pragma unroll
                for (int q = 0; q < 4; q++) c[mt][n][q] = 0.f;

        #pragma unroll
        for (int np = 0; np < 2; np++) {
            uint32_t bfr[4][4];
            #pragma unroll
            for (int ks = 0; ks < 4; ks++) {
                const int rB = 16 * ks + wl + ((sel & 1) << 3);
                const int uB = wid * 4 + 2 * np + (sel >> 1);
                ldsm4t(bfr[ks], sAb + rB * 512 + ((uB ^ (rB & 7)) << 4));
            }
            #pragma unroll
            for (int mt = 0; mt < 4; mt++) {
                #pragma unroll
                for (int ks = 0; ks < 4; ks++) {
                    uint32_t afr[4];
                    const int rA = mt * 16 + wl + ((sel & 1) << 3);
                    const int uA = 2 * ks + (sel >> 1);
                    ldsm4(afr, sWb + mat * 8192 + rA * 128 + ((uA ^ (rA & 7)) << 4));
                    mma16816(c[mt][2 * np],     afr, bfr[ks]);
                    mma16816(c[mt][2 * np + 1], afr, bfr[ks] + 2);
                }
            }
        }

        if (mat > 0) __syncthreads();

        if (mat < 2) {
            // q/k: stage as e4m3, rows of 256B (16 units), unit-swizzled
            #pragma unroll
            for (int mt = 0; mt < 4; mt++) {
                const int o0 = mt * 16 + lr, o1 = o0 + 8;
                const float b0 = sB[mat * 64 + o0];
                const float b1 = sB[mat * 64 + o1];
                #pragma unroll
                for (int j = 0; j < 4; j++) {
                    const int colp = wp0 + j * 8 + 2 * lc;
                    const int pu = colp >> 4, pb = colp & 15;
                    *(uint16_t*)(sStage + o0 * 256 + ((pu ^ (o0 & 7)) << 4) + pb)
                        = pack8(c[mt][j][0] + b0, c[mt][j][1] + b0);
                    *(uint16_t*)(sStage + o1 * 256 + ((pu ^ (o1 & 7)) << 4) + pb)
                        = pack8(c[mt][j][2] + b1, c[mt][j][3] + b1);
                }
            }
            __syncthreads();

            unsigned char* g8 = (mat == 0) ? g_q : g_k;
            #pragma unroll
            for (int oo = 0; oo < 8; oo++) {
                const int o = wid * 8 + oo;
                const uint2 val = *(const uint2*)(sStage + o * 256 +
                    (((lane >> 1) ^ (o & 7)) << 4) + (lane & 1) * 8);
                *(uint2*)(g8 + (size_t)(b * 64 + o) * 65536 + P0 + lane * 8) = val;
            }
        } else {
            // v: stage as fp16, rows of 512B (R12 path)
            #pragma unroll
            for (int mt = 0; mt < 4; mt++) {
                const int o0 = mt * 16 + lr, o1 = o0 + 8;
                const float b0 = sB[mat * 64 + o0];
                const float b1 = sB[mat * 64 + o1];
                #pragma unroll
                for (int j = 0; j < 4; j++) {
                    const int colp = wp0 + j * 8 + 2 * lc;
                    const int pu = colp >> 3, pb = (colp & 7) * 2;
                    *(uint32_t*)(sStage + o0 * 512 + ((pu ^ (o0 & 7)) << 4) + pb)
                        = packh2(c[mt][j][0] + b0, c[mt][j][1] + b0);
                    *(uint32_t*)(sStage + o1 * 512 + ((pu ^ (o1 & 7)) << 4) + pb)
                        = packh2(c[mt][j][2] + b1, c[mt][j][3] + b1);
                }
            }
            __syncthreads();

            #pragma unroll
            for (int oo = 0; oo < 8; oo++) {
                const int o = wid * 8 + oo;
                const uint4 val = *(const uint4*)(sStage + o * 512 + ((lane ^ (o & 7)) << 4));
                *(uint4*)(g_v + (size_t)(b * 64 + o) * 65536 + P0 + lane * 8) = val;
            }
        }
    }
}

// ======================= Kernel B: attention ===============================
// R12 phase structure. S-phase on fp8 (Q/K e4m3, 256B rows, mma k32);
// P/V fp16 (PV identical to R12). P1 overlays the 16KB Q region.
// smem: sQ/P1 @0 (16K); K half / V-ring @16384 (64K); P0 @81920 (16K);
//       sSum @98304 (1K). Total 99328 B, 2 CTAs/SM.
#define AT_Q    0
#define AT_K    16384
#define AT_P0   81920
#define AT_SUM  98304
#define ATTN_SMEM_BYTES 99328

__global__ __launch_bounds__(256, 2) void attn_kernel(
    const float* __restrict__ a,
    const float* __restrict__ Wad,
    float* __restrict__ out)
{
    extern __shared__ char sm[];
    float* sSum = (float*)(sm + AT_SUM);

    const int tid = threadIdx.x, wid = tid >> 5, lane = tid & 31;
    const int rg = wid & 1, cg = wid >> 1;
    const int R0 = rg * 32;
    const int C0 = cg * 32;
    const int V0 = cg * 64;
    const int bc = blockIdx.x >> 2, qq = blockIdx.x & 3;
    const size_t base = (size_t)bc * 65536;

    const int sel = lane >> 3, wl = lane & 7;
    const int lr = lane >> 2, lc = lane & 3;
    const uint32_t sQb = su32(sm + AT_Q), sKb = su32(sm + AT_K), sP0b = su32(sm + AT_P0);

    // ---- async fills: Q fp8 (64 rows x 256B) + K half 0 fp8 (128 x 256B) ----
    {
        const unsigned char* src = g_q + base + (size_t)qq * 16384;
        #pragma unroll
        for (int t = 0; t < 4; t++) {
            const int i = t * 256 + tid;
            const int r = i >> 4, u = i & 15;
            cp16(sQb + r * 256 + ((u ^ (r & 7)) << 4), src + i * 16);
        }
    }
    {
        const unsigned char* src = g_k + base;
        #pragma unroll
        for (int t = 0; t < 8; t++) {
            const int i = t * 256 + tid;
            const int r = i >> 4, u = i & 15;
            cp16(sKb + r * 256 + ((u ^ (r & 7)) << 4), src + i * 16);
        }
    }
    CP_COMMIT();

    float sacc[2][2] = {{0.f, 0.f}, {0.f, 0.f}};
    const float KS = 1.4426950408889634f / 16.f;   // log2(e)/16

    CP_WAIT0();
    __syncthreads();

    // ================= S phases (both K halves), fp8 mma k32 ===============
    for (int kh = 0; kh < 2; kh++) {
        float c[2][4][4];
        #pragma unroll
        for (int mi = 0; mi < 2; mi++)
            #pragma unroll
            for (int n = 0; n < 4; n++)
                #pragma unroll
                for (int q = 0; q < 4; q++) c[mi][n][q] = 0.f;

        for (int ks = 0; ks < 8; ks++) {
            uint32_t a0[4], a1[4];
            {
                const int r = R0 + wl + ((sel & 1) << 3);
                const int u = 2 * ks + (sel >> 1);
                ldsm4(a0, sQb + r * 256 + ((u ^ (r & 7)) << 4));
                const int r2 = r + 16;
                ldsm4(a1, sQb + r2 * 256 + ((u ^ (r2 & 7)) << 4));
            }
            #pragma unroll
            for (int nb = 0; nb < 2; nb++) {
                uint32_t bb[4];
                const int rB = C0 + nb * 16 + wl + ((sel >> 1) << 3);
                const int uB = 2 * ks + (sel & 1);
                ldsm4(bb, sKb + rB * 256 + ((uB ^ (rB & 7)) << 4));
                mma16832(c[0][2 * nb],     a0, bb);
                mma16832(c[0][2 * nb + 1], a0, bb + 2);
                mma16832(c[1][2 * nb],     a1, bb);
                mma16832(c[1][2 * nb + 1], a1, bb + 2);
            }
        }
        __syncthreads();   // K half (and Q, when kh=1) reads done

        if (kh == 0) {
            const unsigned char* src = g_k + base + 32768;   // K half 1 (fp8)
            #pragma unroll
            for (int t = 0; t < 8; t++) {
                const int i = t * 256 + tid;
                const int r = i >> 4, u = i & 15;
                cp16(sKb + r * 256 + ((u ^ (r & 7)) << 4), src + i * 16);
            }
        } else {
            const __half* src = g_v + base;     // V chunk 0 (fp16) -> ring buf 0
            #pragma unroll
            for (int t = 0; t < 8; t++) {
                const int i = t * 256 + tid;
                const int r = i >> 5, u = i & 31;
                cp16(sKb + r * 512 + ((u ^ (r & 7)) << 4), src + i * 8);
            }
        }
        CP_COMMIT();

        // exp (fixed 2^-8 shift) -> P tile fp16 (kh0: P0; kh1: dead Q region)
        const uint32_t pBase = (kh == 0) ? (uint32_t)AT_P0 : (uint32_t)AT_Q;
        #pragma unroll
        for (int mi = 0; mi < 2; mi++) {
            const int rb = R0 + 16 * mi + lr, rb8 = rb + 8;
            #pragma unroll
            for (int ni = 0; ni < 4; ni++) {
                const float e0 = ex2f(fmaf(c[mi][ni][0], KS, -8.f));
                const float e1 = ex2f(fmaf(c[mi][ni][1], KS, -8.f));
                const float e2 = ex2f(fmaf(c[mi][ni][2], KS, -8.f));
                const float e3 = ex2f(fmaf(c[mi][ni][3], KS, -8.f));
                sacc[mi][0] += e0 + e1;
                sacc[mi][1] += e2 + e3;
                const int u = (C0 >> 3) + ni;
                *(uint32_t*)(sm + pBase + rb * 256 + ((u ^ (rb & 7)) << 4) + 4 * lc)
                    = packh2(e0, e1);
                *(uint32_t*)(sm + pBase + rb8 * 256 + ((u ^ (rb8 & 7)) << 4) + 4 * lc)
                    = packh2(e2, e3);
            }
        }
        CP_WAIT0();
        __syncthreads();   // next data ready; P visible
    }

    // ================= PV: 4 chunks of 64 V-rows, 2x32KB ring (fp16) =======
    float o[2][8][4];
    #pragma unroll
    for (int mi = 0; mi < 2; mi++)
        #pragma unroll
        for (int n = 0; n < 8; n++)
            #pragma unroll
            for (int q = 0; q < 4; q++) o[mi][n][q] = 0.f;

    for (int ch = 0; ch < 4; ch++) {
        if (ch < 3) {
            const __half* src = g_v + base + (size_t)(ch + 1) * 16384;
            const uint32_t dst = sKb + (uint32_t)(((ch + 1) & 1) * 32768);
            #pragma unroll
            for (int t = 0; t < 8; t++) {
                const int i = t * 256 + tid;
                const int r = i >> 5, u = i & 31;
                cp16(dst + r * 512 + ((u ^ (r & 7)) << 4), src + i * 8);
            }
            CP_COMMIT();
        }

        const uint32_t vbuf = sKb + (uint32_t)((ch & 1) * 32768);
        const uint32_t pb = (ch < 2) ? sP0b : sQb;
        const int ko = (ch & 1) * 4;

        for (int ks = 0; ks < 4; ks++) {
            uint32_t p0[4], p1[4];
            {
                const int r = R0 + wl + ((sel & 1) << 3);
                const int u = 2 * (ko + ks) + (sel >> 1);
                ldsm4(p0, pb + r * 256 + ((u ^ (r & 7)) << 4));
                const int r2 = r + 16;
                ldsm4(p1, pb + r2 * 256 + ((u ^ (r2 & 7)) << 4));
            }
            #pragma unroll
            for (int nt = 0; nt < 4; nt++) {
                uint32_t bb[4];
                const int rV = 16 * ks + wl + ((sel & 1) << 3);
                const int uV = cg * 8 + 2 * nt + (sel >> 1);
                ldsm4t(bb, vbuf + rV * 512 + ((uV ^ (rV & 7)) << 4));
                mma16816(o[0][2 * nt],     p0, bb);
                mma16816(o[0][2 * nt + 1], p0, bb + 2);
                mma16816(o[1][2 * nt],     p1, bb);
                mma16816(o[1][2 * nt + 1], p1, bb + 2);
            }
        }

        if (ch < 3) {
            CP_WAIT0();
            __syncthreads();
        }
    }

    // ---- quad reduction: full row sums ----
    #pragma unroll
    for (int mi = 0; mi < 2; mi++) {
        #pragma unroll
        for (int hh = 0; hh < 2; hh++) {
            sacc[mi][hh] += __shfl_xor_sync(0xffffffffu, sacc[mi][hh], 1);
            sacc[mi][hh] += __shfl_xor_sync(0xffffffffu, sacc[mi][hh], 2);
        }
    }
    if (lc == 0) {
        #pragma unroll
        for (int mi = 0; mi < 2; mi++) {
            sSum[(R0 + 16 * mi + lr) * 4 + cg]     = sacc[mi][0];
            sSum[(R0 + 16 * mi + lr + 8) * 4 + cg] = sacc[mi][1];
        }
    }
    __syncthreads();

    // ---- epilogue: out = a + wad/rowsum * O ----
    const float wad = Wad[0];
    #pragma unroll
    for (int mi = 0; mi < 2; mi++) {
        const int rb = R0 + 16 * mi + lr;
        const float f0 = wad / (sSum[rb * 4] + sSum[rb * 4 + 1]
                              + sSum[rb * 4 + 2] + sSum[rb * 4 + 3]);
        const float f1 = wad / (sSum[(rb + 8) * 4] + sSum[(rb + 8) * 4 + 1]
                              + sSum[(rb + 8) * 4 + 2] + sSum[(rb + 8) * 4 + 3]);
        const int h0 = qq * 64 + rb;
        #pragma unroll
        for (int ni = 0; ni < 8; ni++) {
            const int col = V0 + ni * 8 + 2 * lc;
            const size_t i0 = base + (size_t)h0 * 256 + col;
            const float2 a0 = *(const float2*)(a + i0);
            float2 v0;
            v0.x = a0.x + f0 * o[mi][ni][0];
            v0.y = a0.y + f0 * o[mi][ni][1];
            *(float2*)(out + i0) = v0;
            const size_t i1 = i0 + 8 * 256;
            const float2 a1 = *(const float2*)(a + i1);
            float2 v1;
            v1.x = a1.x + f1 * o[mi][ni][2];
            v1.y = a1.y + f1 * o[mi][ni][3];
            *(float2*)(out + i1) = v1;
        }
    }
}

// ---------------------------------------------------------------------------
extern "C" void kernel_launch(void* const* d_in, const int* in_sizes, int n_in,
                              void* d_out, int out_size)
{
    const float* a   = (const float*)d_in[0];
    const float* Wq  = (const float*)d_in[1];
    const float* bq  = (const float*)d_in[2];
    const float* Wk  = (const float*)d_in[3];
    const float* bk  = (const float*)d_in[4];
    const float* Wv  = (const float*)d_in[5];
    const float* bv  = (const float*)d_in[6];
    const float* Wad = (const float*)d_in[7];
    float* out = (float*)d_out;

    cudaFuncSetAttribute(qkv_kernel,
                         cudaFuncAttributeMaxDynamicSharedMemorySize, QKV_SMEM_BYTES);
    cudaFuncSetAttribute(attn_kernel,
                         cudaFuncAttributeMaxDynamicSharedMemorySize, ATTN_SMEM_BYTES);
    cudaFuncSetAttribute(attn_kernel,
                         cudaFuncAttributePreferredSharedMemoryCarveout, 100);

    qkv_kernel<<<16 * 256, 256, QKV_SMEM_BYTES>>>(a, Wq, bq, Wk, bk, Wv, bv);
    attn_kernel<<<4096, 256, ATTN_SMEM_BYTES>>>(a, Wad, out);
}